// round 2
// baseline (speedup 1.0000x reference)
#include <cuda_runtime.h>

// Problem constants (fixed shapes from reference setup_inputs)
#define B_  2
#define D_  1024
#define L_  2048
#define NH  8
#define H_  128        // D_/NH
#define TLL 256        // l-tile per block (2 l per thread, 128 threads)
#define TM  128        // m-tile
#define KSZ 384        // reversed-k smem segment

typedef unsigned long long u64;

__device__ __forceinline__ u64 pack2(float x, float y) {
    u64 r; asm("mov.b64 %0, {%1,%2};" : "=l"(r) : "f"(x), "f"(y)); return r;
}
__device__ __forceinline__ float lo2(u64 v) {
    float x, y; asm("mov.b64 {%0,%1}, %2;" : "=f"(x), "=f"(y) : "l"(v)); return x;
}
__device__ __forceinline__ float hsum2(u64 v) {
    float x, y; asm("mov.b64 {%0,%1}, %2;" : "=f"(x), "=f"(y) : "l"(v)); return x + y;
}
__device__ __forceinline__ u64 fma2(u64 a, u64 b, u64 c) {
    u64 d; asm("fma.rn.f32x2 %0, %1, %2, %3;" : "=l"(d) : "l"(a), "l"(b), "l"(c)); return d;
}
__device__ __forceinline__ u64 mul2(u64 a, u64 b) {
    u64 d; asm("mul.rn.f32x2 %0, %1, %2;" : "=l"(d) : "l"(a), "l"(b)); return d;
}

__global__ __launch_bounds__(128)
void hyena_conv_kernel(const float* __restrict__ v,
                       const float* __restrict__ k,
                       const float* __restrict__ bias,
                       const float* __restrict__ x1,
                       const float* __restrict__ x2,
                       float* __restrict__ out)
{
    __shared__ __align__(16) float vsm[NH][TM];    // [i][m]
    __shared__ __align__(16) float x2sm[NH][TM];   // [j][m]
    __shared__ __align__(16) float kr[KSZ];        // reversed filter segment
    __shared__ float bsm[NH];

    const int tid = threadIdx.x;
    const int blk = blockIdx.x;              // ((b*H_ + h) * (L_/TLL) + lt)
    const int ntl = L_ / TLL;                // 8
    const int lt  = blk % ntl;
    const int bh  = blk / ntl;
    const int h   = bh % H_;
    const int b   = bh / H_;
    const int L0  = lt * TLL;

    const float* vb  = v  + ((size_t)b * D_ + (size_t)h * NH) * L_;
    const float* x1b = x1 + ((size_t)b * D_ + (size_t)h * NH) * L_;
    const float* x2b = x2 + ((size_t)b * D_ + (size_t)h * NH) * L_;
    const float* kh  = k  + (size_t)h * L_;
    float*       ob  = out + ((size_t)b * D_ + (size_t)h * NH) * L_;

    if (tid < NH) bsm[tid] = bias[h * NH + tid];

    // x1 gate splats for this thread's two l's
    u64 x1p0[NH], x1p1[NH];
    #pragma unroll
    for (int i = 0; i < NH; i++) {
        float a = x1b[i * L_ + L0 + tid];
        float c = x1b[i * L_ + L0 + 128 + tid];
        x1p0[i] = pack2(a, a);
        x1p1[i] = pack2(c, c);
    }

    // acc[j] lanes = (sum over even m, sum over odd m)
    u64 acc0[NH], acc1[NH];
    #pragma unroll
    for (int j = 0; j < NH; j++) { acc0[j] = 0; acc1[j] = 0; }

    const int e0 = 255 - tid;   // kr index base for l0 = L0 + tid
    const int e1 = 127 - tid;   // kr index base for l1 = L0 + 128 + tid

    const int nmt = L0 / TM + 2;  // causal m-tiles: M0 <= L0 + TLL - 1
    for (int mt = 0; mt < nmt; mt++) {
        const int M0    = mt * TM;
        const int kbase = L0 + 255 - M0;   // kr[e] = k[kbase - e]

        __syncthreads();
        #pragma unroll
        for (int i = 0; i < NH; i++) vsm[i][tid]  = vb[i * L_ + M0 + tid];
        #pragma unroll
        for (int j = 0; j < NH; j++) x2sm[j][tid] = x2b[j * L_ + M0 + tid];
        #pragma unroll
        for (int q = 0; q < 3; q++) {
            int e   = tid + q * 128;
            int idx = kbase - e;
            kr[e] = (idx >= 0) ? kh[idx] : 0.0f;   // zero-pad = causality
        }
        __syncthreads();

        #pragma unroll 2
        for (int mi = 0; mi < TM; mi += 4) {
            // s = A[l, m-pair] = sum_i x1[i,l] * v[i, m-pair]
            u64 sa0, sa1, sb0, sb1;
            {
                float4 vq = *(const float4*)&vsm[0][mi];    // broadcast LDS.128
                u64 vlo = pack2(vq.x, vq.y), vhi = pack2(vq.z, vq.w);
                sa0 = mul2(x1p0[0], vlo); sa1 = mul2(x1p0[0], vhi);
                sb0 = mul2(x1p1[0], vlo); sb1 = mul2(x1p1[0], vhi);
            }
            #pragma unroll
            for (int i = 1; i < NH; i++) {
                float4 vq = *(const float4*)&vsm[i][mi];
                u64 vlo = pack2(vq.x, vq.y), vhi = pack2(vq.z, vq.w);
                sa0 = fma2(x1p0[i], vlo, sa0); sa1 = fma2(x1p0[i], vhi, sa1);
                sb0 = fma2(x1p1[i], vlo, sb0); sb1 = fma2(x1p1[i], vhi, sb1);
            }

            // Toeplitz taps (ascending in m thanks to reversed kr layout)
            const float* ka = &kr[e0 + mi];
            const float* kb = &kr[e1 + mi];
            u64 ta0 = mul2(pack2(ka[0], ka[1]), sa0);
            u64 ta1 = mul2(pack2(ka[2], ka[3]), sa1);
            u64 tb0 = mul2(pack2(kb[0], kb[1]), sb0);
            u64 tb1 = mul2(pack2(kb[2], kb[3]), sb1);

            // acc[j] += t(m-pair) * x2[j, m-pair]
            #pragma unroll
            for (int j = 0; j < NH; j++) {
                float4 xq = *(const float4*)&x2sm[j][mi];   // broadcast LDS.128
                u64 xlo = pack2(xq.x, xq.y), xhi = pack2(xq.z, xq.w);
                acc0[j] = fma2(ta0, xlo, acc0[j]);
                acc0[j] = fma2(ta1, xhi, acc0[j]);
                acc1[j] = fma2(tb0, xlo, acc1[j]);
                acc1[j] = fma2(tb1, xhi, acc1[j]);
            }
        }
    }

    // Epilogue: horizontal add + skip/bias term, then store.
    {
        int l = L0 + tid;
        float sb = 0.0f;
        #pragma unroll
        for (int i = 0; i < NH; i++) sb += lo2(x1p0[i]) * bsm[i] * vb[i * L_ + l];
        #pragma unroll
        for (int j = 0; j < NH; j++)
            ob[j * L_ + l] = hsum2(acc0[j]) + sb * x2b[j * L_ + l];
    }
    {
        int l = L0 + 128 + tid;
        float sb = 0.0f;
        #pragma unroll
        for (int i = 0; i < NH; i++) sb += lo2(x1p1[i]) * bsm[i] * vb[i * L_ + l];
        #pragma unroll
        for (int j = 0; j < NH; j++)
            ob[j * L_ + l] = hsum2(acc1[j]) + sb * x2b[j * L_ + l];
    }
}

extern "C" void kernel_launch(void* const* d_in, const int* in_sizes, int n_in,
                              void* d_out, int out_size)
{
    const float* v    = (const float*)d_in[0];
    const float* k    = (const float*)d_in[1];
    const float* bias = (const float*)d_in[2];
    const float* x1   = (const float*)d_in[3];
    const float* x2   = (const float*)d_in[4];
    // d_in[5] = num_heads (int32) — shapes fixed, NH hardcoded to 8.
    float* out = (float*)d_out;

    dim3 grid(B_ * H_ * (L_ / TLL));   // 2048 blocks
    hyena_conv_kernel<<<grid, 128>>>(v, k, bias, x1, x2, out);
}

// round 3
// speedup vs baseline: 1.1436x; 1.1436x over previous
#include <cuda_runtime.h>

// Problem constants (fixed shapes from reference setup_inputs)
#define B_  2
#define D_  1024
#define L_  2048
#define NH  8
#define H_  128        // D_/NH
#define TLL 256        // l-tile per block (2 l per thread, 128 threads)
#define TM  128        // m-tile
#define KSZ 384        // reversed-k smem segment
#define KPL 2560       // padded reversed-k row length (2048 + 512 zeros)

typedef unsigned long long u64;

// Reversed + zero-padded filter: g_kprev[h][j] = k[h, L-1-j] for j<L, else 0.
__device__ __align__(16) float g_kprev[H_ * KPL];

__device__ __forceinline__ u64 pack2(float x, float y) {
    u64 r; asm("mov.b64 %0, {%1,%2};" : "=l"(r) : "f"(x), "f"(y)); return r;
}
__device__ __forceinline__ float lo2(u64 v) {
    float x, y; asm("mov.b64 {%0,%1}, %2;" : "=f"(x), "=f"(y) : "l"(v)); return x;
}
__device__ __forceinline__ float hsum2(u64 v) {
    float x, y; asm("mov.b64 {%0,%1}, %2;" : "=f"(x), "=f"(y) : "l"(v)); return x + y;
}
__device__ __forceinline__ u64 fma2(u64 a, u64 b, u64 c) {
    u64 d; asm("fma.rn.f32x2 %0, %1, %2, %3;" : "=l"(d) : "l"(a), "l"(b), "l"(c)); return d;
}
__device__ __forceinline__ u64 mul2(u64 a, u64 b) {
    u64 d; asm("mul.rn.f32x2 %0, %1, %2;" : "=l"(d) : "l"(a), "l"(b)); return d;
}
__device__ __forceinline__ void cpasync16(void* dst, const void* src) {
    unsigned d = (unsigned)__cvta_generic_to_shared(dst);
    asm volatile("cp.async.ca.shared.global [%0], [%1], 16;" :: "r"(d), "l"(src));
}
__device__ __forceinline__ void cp_commit() {
    asm volatile("cp.async.commit_group;" ::: "memory");
}

__global__ void build_kprev(const float* __restrict__ k) {
    int idx = blockIdx.x * 256 + threadIdx.x;
    if (idx >= H_ * KPL) return;
    int h = idx / KPL, j = idx % KPL;
    g_kprev[idx] = (j < L_) ? k[h * L_ + (L_ - 1 - j)] : 0.0f;
}

__global__ __launch_bounds__(128, 5)
void hyena_conv_kernel(const float* __restrict__ v,
                       const float* __restrict__ bias,
                       const float* __restrict__ x1,
                       const float* __restrict__ x2,
                       float* __restrict__ out)
{
    __shared__ __align__(16) float vsm[2][NH][TM];    // [stage][i][m]
    __shared__ __align__(16) float x2sm[2][NH][TM];   // [stage][j][m]
    __shared__ __align__(16) float kr[2][KSZ];        // [stage][e] reversed taps
    __shared__ float bsm[NH];

    const int tid = threadIdx.x;
    const int blk = blockIdx.x;
    // LPT: heaviest l-tiles first (lt descending as blk grows slow-index)
    const int bh = blk & 255;               // b*H_ + h
    const int lt = 7 - (blk >> 8);          // ntl-1 ... 0
    const int h  = bh & 127;
    const int b  = bh >> 7;
    const int L0 = lt * TLL;

    const float* vb  = v  + ((size_t)b * D_ + (size_t)h * NH) * L_;
    const float* x1b = x1 + ((size_t)b * D_ + (size_t)h * NH) * L_;
    const float* x2b = x2 + ((size_t)b * D_ + (size_t)h * NH) * L_;
    const float* kp  = g_kprev + (size_t)h * KPL + (L_ - 256 - L0);
    float*       ob  = out + ((size_t)b * D_ + (size_t)h * NH) * L_;

    const int nmt = L0 / TM + 2;            // causal m-tiles

    // --- async tile issue: v/x2 tiles (8x128 each) + reversed k segment ---
    const int c0i = tid >> 5,          c0m = (tid & 31) << 2;
    const int c1i = (tid + 128) >> 5,  c1m = (tid & 31) << 2;  // c1 = tid+128
    auto issue = [&](int mt_) {
        const int p  = mt_ & 1;
        const int M0 = mt_ * TM;
        cpasync16(&vsm [p][c0i][c0m], vb  + c0i * L_ + M0 + c0m);
        cpasync16(&x2sm[p][c0i][c0m], x2b + c0i * L_ + M0 + c0m);
        cpasync16(&vsm [p][c1i][c1m], vb  + c1i * L_ + M0 + c1m);
        cpasync16(&x2sm[p][c1i][c1m], x2b + c1i * L_ + M0 + c1m);
        if (tid < 96) cpasync16(&kr[p][tid * 4], kp + M0 + tid * 4);
        cp_commit();
    };

    issue(0);
    if (nmt > 1) issue(1);

    if (tid < NH) bsm[tid] = bias[h * NH + tid];

    // x1 gate splats for this thread's two l's (overlaps with cp.async)
    u64 x1p0[NH], x1p1[NH];
    #pragma unroll
    for (int i = 0; i < NH; i++) {
        float a = x1b[i * L_ + L0 + tid];
        float c = x1b[i * L_ + L0 + 128 + tid];
        x1p0[i] = pack2(a, a);
        x1p1[i] = pack2(c, c);
    }

    // acc[j] lanes = (sum over even m, sum over odd m)
    u64 acc0[NH], acc1[NH];
    #pragma unroll
    for (int j = 0; j < NH; j++) { acc0[j] = 0; acc1[j] = 0; }

    const int e0 = 255 - tid;   // kr index base for l0 = L0 + tid
    const int e1 = 127 - tid;   // kr index base for l1 = L0 + 128 + tid

    for (int mt = 0; mt < nmt; mt++) {
        if (mt == nmt - 1) asm volatile("cp.async.wait_group 0;" ::: "memory");
        else               asm volatile("cp.async.wait_group 1;" ::: "memory");
        __syncthreads();

        const int p = mt & 1;
        const float (*vt)[TM]  = vsm[p];
        const float (*x2t)[TM] = x2sm[p];
        const float *krt       = kr[p];

        #pragma unroll 2
        for (int mi = 0; mi < TM; mi += 4) {
            // s = A[l, m-quad] = sum_i x1[i,l] * v[i, m-quad]
            u64 sa0, sa1, sb0, sb1;
            {
                double2 vq = *(const double2*)&vt[0][mi];   // LDS.128 -> 2 reg pairs
                u64 vlo = __double_as_longlong(vq.x);
                u64 vhi = __double_as_longlong(vq.y);
                sa0 = mul2(x1p0[0], vlo); sa1 = mul2(x1p0[0], vhi);
                sb0 = mul2(x1p1[0], vlo); sb1 = mul2(x1p1[0], vhi);
            }
            #pragma unroll
            for (int i = 1; i < NH; i++) {
                double2 vq = *(const double2*)&vt[i][mi];
                u64 vlo = __double_as_longlong(vq.x);
                u64 vhi = __double_as_longlong(vq.y);
                sa0 = fma2(x1p0[i], vlo, sa0); sa1 = fma2(x1p0[i], vhi, sa1);
                sb0 = fma2(x1p1[i], vlo, sb0); sb1 = fma2(x1p1[i], vhi, sb1);
            }

            // Toeplitz taps (ascending in m thanks to reversed layout)
            const float* ka = &krt[e0 + mi];
            const float* kb = &krt[e1 + mi];
            u64 ta0 = mul2(pack2(ka[0], ka[1]), sa0);
            u64 ta1 = mul2(pack2(ka[2], ka[3]), sa1);
            u64 tb0 = mul2(pack2(kb[0], kb[1]), sb0);
            u64 tb1 = mul2(pack2(kb[2], kb[3]), sb1);

            // acc[j] += t(m-quad) * x2[j, m-quad]
            #pragma unroll
            for (int j = 0; j < NH; j++) {
                double2 xq = *(const double2*)&x2t[j][mi];
                u64 xlo = __double_as_longlong(xq.x);
                u64 xhi = __double_as_longlong(xq.y);
                acc0[j] = fma2(ta0, xlo, acc0[j]);
                acc0[j] = fma2(ta1, xhi, acc0[j]);
                acc1[j] = fma2(tb0, xlo, acc1[j]);
                acc1[j] = fma2(tb1, xhi, acc1[j]);
            }
        }

        __syncthreads();            // compute(p) done before re-filling stage p
        if (mt + 2 < nmt) issue(mt + 2);
    }

    // Epilogue: horizontal add + skip/bias term, then store.
    {
        int l = L0 + tid;
        float sb = 0.0f;
        #pragma unroll
        for (int i = 0; i < NH; i++) sb += lo2(x1p0[i]) * bsm[i] * vb[i * L_ + l];
        #pragma unroll
        for (int j = 0; j < NH; j++)
            ob[j * L_ + l] = hsum2(acc0[j]) + sb * x2b[j * L_ + l];
    }
    {
        int l = L0 + 128 + tid;
        float sb = 0.0f;
        #pragma unroll
        for (int i = 0; i < NH; i++) sb += lo2(x1p1[i]) * bsm[i] * vb[i * L_ + l];
        #pragma unroll
        for (int j = 0; j < NH; j++)
            ob[j * L_ + l] = hsum2(acc1[j]) + sb * x2b[j * L_ + l];
    }
}

extern "C" void kernel_launch(void* const* d_in, const int* in_sizes, int n_in,
                              void* d_out, int out_size)
{
    const float* v    = (const float*)d_in[0];
    const float* k    = (const float*)d_in[1];
    const float* bias = (const float*)d_in[2];
    const float* x1   = (const float*)d_in[3];
    const float* x2   = (const float*)d_in[4];
    // d_in[5] = num_heads (int32) — shapes fixed, NH hardcoded to 8.
    float* out = (float*)d_out;

    build_kprev<<<(H_ * KPL + 255) / 256, 256>>>(k);
    dim3 grid(B_ * H_ * (L_ / TLL));   // 2048 blocks, heavy l-tiles first
    hyena_conv_kernel<<<grid, 128>>>(v, bias, x1, x2, out);
}